// round 2
// baseline (speedup 1.0000x reference)
// R1: resubmission of R0 kernel — previous round failed on GB300 container
// infra ("container failed twice"), not on kernel compile/run. No code change.
#include <cuda_runtime.h>

#define BB  8
#define TT  1024
#define EE  1024
#define HH  16
#define HSZ 64
#define MTOT (BB*TT)   // 8192

// Scratch (static device arrays: allocation-free per harness rules)
__device__ __align__(16) float g_q[BB*HH*TT*HSZ];
__device__ __align__(16) float g_k[BB*HH*TT*HSZ];
__device__ __align__(16) float g_v[BB*HH*TT*HSZ];
__device__ __align__(16) float g_att[BB*TT*EE];

// ---------------------------------------------------------------------------
// FP32 GEMM: C = A @ W^T ;  A [M,1024] row-major, W [1024,1024] row-major
// 128x128 block tile, BK=8, 256 threads, 8x8 per-thread register tile.
// ---------------------------------------------------------------------------
#define GBM 128
#define GBN 128
#define GBK 8
#define GLD (GBM + 4)   // 132 floats: 528B row stride, 16B aligned, conflict-free

__device__ __forceinline__ void gemm_tile_128(
    const float* __restrict__ A, const float* __restrict__ W,
    int blockM, int blockN, float acc[8][8], float* As, float* Bs)
{
    const int tid = threadIdx.x;
    const int tx = tid & 15, ty = tid >> 4;
    const int ar = tid >> 1;          // 0..127
    const int ac = (tid & 1) * 4;     // 0 or 4
    const float* Aptr = A + (size_t)(blockM + ar) * EE + ac;
    const float* Wptr = W + (size_t)(blockN + ar) * EE + ac;

    float4 fa = *(const float4*)Aptr;
    float4 fb = *(const float4*)Wptr;

    #pragma unroll 1
    for (int kt = 0; kt < EE / GBK; ++kt) {
        // stage current tile to smem (transposed: [k][m] / [k][n])
        As[(ac+0)*GLD + ar] = fa.x; As[(ac+1)*GLD + ar] = fa.y;
        As[(ac+2)*GLD + ar] = fa.z; As[(ac+3)*GLD + ar] = fa.w;
        Bs[(ac+0)*GLD + ar] = fb.x; Bs[(ac+1)*GLD + ar] = fb.y;
        Bs[(ac+2)*GLD + ar] = fb.z; Bs[(ac+3)*GLD + ar] = fb.w;
        __syncthreads();
        if (kt + 1 < EE / GBK) {   // prefetch next tile into registers
            fa = *(const float4*)(Aptr + (kt+1)*GBK);
            fb = *(const float4*)(Wptr + (kt+1)*GBK);
        }
        #pragma unroll
        for (int kk = 0; kk < GBK; ++kk) {
            float a0[8], b0[8];
            *(float4*)&a0[0] = *(const float4*)&As[kk*GLD + ty*8];
            *(float4*)&a0[4] = *(const float4*)&As[kk*GLD + ty*8 + 4];
            *(float4*)&b0[0] = *(const float4*)&Bs[kk*GLD + tx*8];
            *(float4*)&b0[4] = *(const float4*)&Bs[kk*GLD + tx*8 + 4];
            #pragma unroll
            for (int i = 0; i < 8; ++i)
                #pragma unroll
                for (int j = 0; j < 8; ++j)
                    acc[i][j] += a0[i] * b0[j];
        }
        __syncthreads();
    }
}

// QKV projection: grid (8, 64, 3); z selects Wq/Wk/Wv; output scattered to
// [B,H,T,HS] layout for the attention stage.
__global__ __launch_bounds__(256) void qkv_gemm_kernel(
    const float* __restrict__ x, const float* __restrict__ Wq,
    const float* __restrict__ Wk, const float* __restrict__ Wv)
{
    __shared__ __align__(16) float As[GBK*GLD];
    __shared__ __align__(16) float Bs[GBK*GLD];
    const int z = blockIdx.z;
    const float* W = (z == 0) ? Wq : (z == 1) ? Wk : Wv;
    float* dst     = (z == 0) ? g_q : (z == 1) ? g_k : g_v;
    const int blockM = blockIdx.y * GBM, blockN = blockIdx.x * GBN;

    float acc[8][8];
    #pragma unroll
    for (int i = 0; i < 8; ++i)
        #pragma unroll
        for (int j = 0; j < 8; ++j) acc[i][j] = 0.f;

    gemm_tile_128(x, W, blockM, blockN, acc, As, Bs);

    const int tx = threadIdx.x & 15, ty = threadIdx.x >> 4;
    #pragma unroll
    for (int i = 0; i < 8; ++i) {
        const int row = blockM + ty*8 + i;
        const int b = row >> 10, t = row & (TT-1);
        #pragma unroll
        for (int j4 = 0; j4 < 2; ++j4) {
            const int col = blockN + tx*8 + j4*4;
            const int h = col >> 6, d = col & 63;
            float4 v4 = make_float4(acc[i][j4*4+0], acc[i][j4*4+1],
                                    acc[i][j4*4+2], acc[i][j4*4+3]);
            *(float4*)&dst[((size_t)(b*HH + h)*TT + t)*HSZ + d] = v4;
        }
    }
}

// Output projection: out = att @ Wproj^T, standard [row][col] store.
__global__ __launch_bounds__(256) void proj_gemm_kernel(
    const float* __restrict__ Wp, float* __restrict__ out)
{
    __shared__ __align__(16) float As[GBK*GLD];
    __shared__ __align__(16) float Bs[GBK*GLD];
    const int blockM = blockIdx.y * GBM, blockN = blockIdx.x * GBN;

    float acc[8][8];
    #pragma unroll
    for (int i = 0; i < 8; ++i)
        #pragma unroll
        for (int j = 0; j < 8; ++j) acc[i][j] = 0.f;

    gemm_tile_128(g_att, Wp, blockM, blockN, acc, As, Bs);

    const int tx = threadIdx.x & 15, ty = threadIdx.x >> 4;
    #pragma unroll
    for (int i = 0; i < 8; ++i) {
        const int row = blockM + ty*8 + i;
        #pragma unroll
        for (int j4 = 0; j4 < 2; ++j4) {
            const int col = blockN + tx*8 + j4*4;
            float4 v4 = make_float4(acc[i][j4*4+0], acc[i][j4*4+1],
                                    acc[i][j4*4+2], acc[i][j4*4+3]);
            *(float4*)&out[(size_t)row*EE + col] = v4;
        }
    }
}

// ---------------------------------------------------------------------------
// Causal flash attention, fp32. Block = (64 q-rows, one (b,h)), 256 threads,
// thread (tx,ty) owns a 4x4 S-tile and a 4x4 O-tile. Q/K stored transposed
// [d][row] in smem so all inner-loop reads are conflict-free float4; P is
// stored transposed into the K buffer (reused), V stays [row][d].
// ---------------------------------------------------------------------------
#define ALD 68   // 64 + 4 pad

__global__ __launch_bounds__(256) void attn_kernel_f32()
{
    extern __shared__ __align__(16) float sm[];
    float* Qst = sm;               // [64][ALD]  Qst[d][row]
    float* KP  = sm + 64*ALD;      // Kst[d][col]  then  Pst[c][row]
    float* Vs  = sm + 2*64*ALD;    // Vs[c][d]

    const int qb = blockIdx.x, h = blockIdx.y, b = blockIdx.z;
    const float* qp = g_q + ((size_t)(b*HH + h)*TT + qb*64)*HSZ;
    const float* kp = g_k + ((size_t)(b*HH + h)*TT)*HSZ;
    const float* vp = g_v + ((size_t)(b*HH + h)*TT)*HSZ;

    const int tid = threadIdx.x;
    const int tx = tid & 15, ty = tid >> 4;
    const int lr  = tid >> 2;          // 0..63
    const int ld0 = (tid & 3) * 16;    // 0,16,32,48

    // Q tile -> smem, transposed
    #pragma unroll
    for (int u = 0; u < 4; ++u) {
        float4 f = *(const float4*)(qp + (size_t)lr*HSZ + ld0 + u*4);
        Qst[(ld0+u*4+0)*ALD + lr] = f.x;
        Qst[(ld0+u*4+1)*ALD + lr] = f.y;
        Qst[(ld0+u*4+2)*ALD + lr] = f.z;
        Qst[(ld0+u*4+3)*ALD + lr] = f.w;
    }

    float m[4], l[4], o[4][4];
    #pragma unroll
    for (int i = 0; i < 4; ++i) {
        m[i] = -1e30f; l[i] = 0.f;
        #pragma unroll
        for (int j = 0; j < 4; ++j) o[i][j] = 0.f;
    }

    const float scl = 0.125f;  // HS^-0.5

    for (int kb = 0; kb <= qb; ++kb) {
        // K (transposed) and V tiles
        #pragma unroll
        for (int u = 0; u < 4; ++u) {
            float4 f = *(const float4*)(kp + (size_t)(kb*64 + lr)*HSZ + ld0 + u*4);
            KP[(ld0+u*4+0)*ALD + lr] = f.x;
            KP[(ld0+u*4+1)*ALD + lr] = f.y;
            KP[(ld0+u*4+2)*ALD + lr] = f.z;
            KP[(ld0+u*4+3)*ALD + lr] = f.w;
            float4 g = *(const float4*)(vp + (size_t)(kb*64 + lr)*HSZ + ld0 + u*4);
            *(float4*)&Vs[lr*ALD + ld0 + u*4] = g;
        }
        __syncthreads();

        // S = Q K^T (4x4 per thread)
        float s[4][4];
        #pragma unroll
        for (int i = 0; i < 4; ++i)
            #pragma unroll
            for (int j = 0; j < 4; ++j) s[i][j] = 0.f;

        #pragma unroll 8
        for (int d = 0; d < 64; ++d) {
            float4 qv = *(const float4*)&Qst[d*ALD + ty*4];
            float4 kv = *(const float4*)&KP [d*ALD + tx*4];
            float qa[4] = {qv.x, qv.y, qv.z, qv.w};
            float ka[4] = {kv.x, kv.y, kv.z, kv.w};
            #pragma unroll
            for (int i = 0; i < 4; ++i)
                #pragma unroll
                for (int j = 0; j < 4; ++j)
                    s[i][j] += qa[i] * ka[j];
        }

        // scale + causal mask (only diagonal block needs masking)
        #pragma unroll
        for (int i = 0; i < 4; ++i)
            #pragma unroll
            for (int j = 0; j < 4; ++j) s[i][j] *= scl;
        if (kb == qb) {
            #pragma unroll
            for (int i = 0; i < 4; ++i)
                #pragma unroll
                for (int j = 0; j < 4; ++j)
                    if (tx*4 + j > ty*4 + i) s[i][j] = -1e30f;
        }

        // online softmax stats (row reductions across the 16 tx lanes)
        float alpha[4];
        #pragma unroll
        for (int i = 0; i < 4; ++i) {
            float rm = fmaxf(fmaxf(s[i][0], s[i][1]), fmaxf(s[i][2], s[i][3]));
            rm = fmaxf(rm, __shfl_xor_sync(0xffffffffu, rm, 8));
            rm = fmaxf(rm, __shfl_xor_sync(0xffffffffu, rm, 4));
            rm = fmaxf(rm, __shfl_xor_sync(0xffffffffu, rm, 2));
            rm = fmaxf(rm, __shfl_xor_sync(0xffffffffu, rm, 1));
            const float mn = fmaxf(m[i], rm);
            alpha[i] = __expf(m[i] - mn);
            m[i] = mn;
            float rs = 0.f;
            #pragma unroll
            for (int j = 0; j < 4; ++j) { s[i][j] = __expf(s[i][j] - mn); rs += s[i][j]; }
            rs += __shfl_xor_sync(0xffffffffu, rs, 8);
            rs += __shfl_xor_sync(0xffffffffu, rs, 4);
            rs += __shfl_xor_sync(0xffffffffu, rs, 2);
            rs += __shfl_xor_sync(0xffffffffu, rs, 1);
            l[i] = l[i]*alpha[i] + rs;
            #pragma unroll
            for (int j = 0; j < 4; ++j) o[i][j] *= alpha[i];
        }

        __syncthreads();                 // all reads of Kst done
        // P -> smem (transposed into KP): Pst[c][row]
        #pragma unroll
        for (int j = 0; j < 4; ++j)
            #pragma unroll
            for (int i = 0; i < 4; ++i)
                KP[(tx*4+j)*ALD + ty*4 + i] = s[i][j];
        __syncthreads();

        // O += P @ V
        #pragma unroll 8
        for (int c = 0; c < 64; ++c) {
            float4 pv = *(const float4*)&KP[c*ALD + ty*4];
            float4 vv = *(const float4*)&Vs[c*ALD + tx*4];
            float pa[4] = {pv.x, pv.y, pv.z, pv.w};
            float va[4] = {vv.x, vv.y, vv.z, vv.w};
            #pragma unroll
            for (int i = 0; i < 4; ++i)
                #pragma unroll
                for (int j = 0; j < 4; ++j)
                    o[i][j] += pa[i] * va[j];
        }
        __syncthreads();                 // before next iter overwrites KP/Vs
    }

    // normalize + store to g_att [B*T, E] with head-concat layout
    float* ap = g_att + ((size_t)b*TT + qb*64)*EE + h*HSZ;
    #pragma unroll
    for (int i = 0; i < 4; ++i) {
        const float inv = 1.0f / l[i];
        float4 v4 = make_float4(o[i][0]*inv, o[i][1]*inv, o[i][2]*inv, o[i][3]*inv);
        *(float4*)&ap[(size_t)(ty*4+i)*EE + tx*4] = v4;
    }
}

// ---------------------------------------------------------------------------
extern "C" void kernel_launch(void* const* d_in, const int* in_sizes, int n_in,
                              void* d_out, int out_size)
{
    const float* x  = (const float*)d_in[0];
    const float* Wk = (const float*)d_in[1];
    const float* Wq = (const float*)d_in[2];
    const float* Wv = (const float*)d_in[3];
    const float* Wp = (const float*)d_in[4];
    float* out = (float*)d_out;

    const int attn_smem = 3 * 64 * ALD * (int)sizeof(float);   // 52224 B
    cudaFuncSetAttribute(attn_kernel_f32,
                         cudaFuncAttributeMaxDynamicSharedMemorySize, attn_smem);

    dim3 gq(EE/GBN, MTOT/GBM, 3);          // (8, 64, 3)
    qkv_gemm_kernel<<<gq, 256>>>(x, Wq, Wk, Wv);

    dim3 ga(TT/64, HH, BB);                // (16, 16, 8)
    attn_kernel_f32<<<ga, 256, attn_smem>>>();

    dim3 gp(EE/GBN, MTOT/GBM);             // (8, 64)
    proj_gemm_kernel<<<gp, 256>>>(Wp, out);
}

// round 3
// speedup vs baseline: 1.0928x; 1.0928x over previous
// R2: weight GEMMs (QKV + proj) -> mma.sync.m16n8k8 TF32 tensor cores,
// fp32 accumulate. Attention stage unchanged (fp32 SIMT).
#include <cuda_runtime.h>

#define BB  8
#define TT  1024
#define EE  1024
#define HH  16
#define HSZ 64
#define MTOT (BB*TT)   // 8192

__device__ __align__(16) float g_q[BB*HH*TT*HSZ];
__device__ __align__(16) float g_k[BB*HH*TT*HSZ];
__device__ __align__(16) float g_v[BB*HH*TT*HSZ];
__device__ __align__(16) float g_att[BB*TT*EE];

// ---------------------------------------------------------------------------
// TF32 tensor-core GEMM: C = A @ W^T. A [M,1024] row-major, W [1024,1024]
// row-major (so W rows are the "col-major B" columns mma expects).
// 128x128 block tile, BK=16, 256 threads = 8 warps (4 m x 2 n),
// warp tile 32x64 = 2 (m16) x 8 (n8) mma tiles. Double-buffered smem.
// ---------------------------------------------------------------------------
#define TBM 128
#define TBN 128
#define TBK 16
#define BKP 20   // padded k-stride: (20*grp+tig)%32 covers all banks once

__device__ __forceinline__ unsigned f2tf32(float f) {
    unsigned r; asm("cvt.rna.tf32.f32 %0, %1;" : "=r"(r) : "f"(f));
    return r;
}

__device__ __forceinline__ void mma_tf32(float c[4],
    unsigned a0, unsigned a1, unsigned a2, unsigned a3,
    unsigned b0, unsigned b1)
{
    asm volatile(
        "mma.sync.aligned.m16n8k8.row.col.f32.tf32.tf32.f32 "
        "{%0,%1,%2,%3}, {%4,%5,%6,%7}, {%8,%9}, {%0,%1,%2,%3};"
        : "+f"(c[0]), "+f"(c[1]), "+f"(c[2]), "+f"(c[3])
        : "r"(a0), "r"(a1), "r"(a2), "r"(a3), "r"(b0), "r"(b1));
}

// Core tile loop. acc[i][j][4] = per-thread fragments for m-tile i, n-tile j.
__device__ __forceinline__ void gemm_tf32_tile(
    const float* __restrict__ A, const float* __restrict__ W,
    int blockM, int blockN, float acc[2][8][4],
    float* As, float* Ws)   // each [2][128*BKP]
{
    const int tid  = threadIdx.x;
    const int wid  = tid >> 5;
    const int lane = tid & 31;
    const int grp  = lane >> 2;     // 0..7
    const int tig  = lane & 3;      // 0..3
    const int warpM = (wid & 3) * 32;
    const int warpN = (wid >> 2) * 64;

    // staging: each thread covers 2 float4 of A and 2 of W per BK=16 tile
    const int r0 = tid >> 2;              // 0..63
    const int r1 = r0 + 64;               // 64..127
    const int cg = (tid & 3) * 4;         // 0,4,8,12
    const float* Ap0 = A + (size_t)(blockM + r0) * EE + cg;
    const float* Ap1 = A + (size_t)(blockM + r1) * EE + cg;
    const float* Wp0 = W + (size_t)(blockN + r0) * EE + cg;
    const float* Wp1 = W + (size_t)(blockN + r1) * EE + cg;

    float4 fa0 = *(const float4*)Ap0;
    float4 fa1 = *(const float4*)Ap1;
    float4 fw0 = *(const float4*)Wp0;
    float4 fw1 = *(const float4*)Wp1;

    const int NKT = EE / TBK;   // 64

    #pragma unroll 1
    for (int kt = 0; kt < NKT; ++kt) {
        float* as = As + (kt & 1) * (TBM * BKP);
        float* ws = Ws + (kt & 1) * (TBM * BKP);

        // stage current tile (convert to tf32 bits once per element)
        as[r0*BKP + cg+0] = __uint_as_float(f2tf32(fa0.x));
        as[r0*BKP + cg+1] = __uint_as_float(f2tf32(fa0.y));
        as[r0*BKP + cg+2] = __uint_as_float(f2tf32(fa0.z));
        as[r0*BKP + cg+3] = __uint_as_float(f2tf32(fa0.w));
        as[r1*BKP + cg+0] = __uint_as_float(f2tf32(fa1.x));
        as[r1*BKP + cg+1] = __uint_as_float(f2tf32(fa1.y));
        as[r1*BKP + cg+2] = __uint_as_float(f2tf32(fa1.z));
        as[r1*BKP + cg+3] = __uint_as_float(f2tf32(fa1.w));
        ws[r0*BKP + cg+0] = __uint_as_float(f2tf32(fw0.x));
        ws[r0*BKP + cg+1] = __uint_as_float(f2tf32(fw0.y));
        ws[r0*BKP + cg+2] = __uint_as_float(f2tf32(fw0.z));
        ws[r0*BKP + cg+3] = __uint_as_float(f2tf32(fw0.w));
        ws[r1*BKP + cg+0] = __uint_as_float(f2tf32(fw1.x));
        ws[r1*BKP + cg+1] = __uint_as_float(f2tf32(fw1.y));
        ws[r1*BKP + cg+2] = __uint_as_float(f2tf32(fw1.z));
        ws[r1*BKP + cg+3] = __uint_as_float(f2tf32(fw1.w));
        __syncthreads();

        if (kt + 1 < NKT) {   // prefetch next tile
            const int ko = (kt + 1) * TBK;
            fa0 = *(const float4*)(Ap0 + ko);
            fa1 = *(const float4*)(Ap1 + ko);
            fw0 = *(const float4*)(Wp0 + ko);
            fw1 = *(const float4*)(Wp1 + ko);
        }

        #pragma unroll
        for (int ks = 0; ks < 2; ++ks) {
            const int k0 = ks * 8;
            unsigned af[2][4], bf[8][2];
            #pragma unroll
            for (int i = 0; i < 2; ++i) {
                const int rb = warpM + i*16;
                af[i][0] = __float_as_uint(as[(rb+grp  )*BKP + k0 + tig    ]);
                af[i][1] = __float_as_uint(as[(rb+grp+8)*BKP + k0 + tig    ]);
                af[i][2] = __float_as_uint(as[(rb+grp  )*BKP + k0 + tig + 4]);
                af[i][3] = __float_as_uint(as[(rb+grp+8)*BKP + k0 + tig + 4]);
            }
            #pragma unroll
            for (int j = 0; j < 8; ++j) {
                const int col = warpN + j*8 + grp;
                bf[j][0] = __float_as_uint(ws[col*BKP + k0 + tig    ]);
                bf[j][1] = __float_as_uint(ws[col*BKP + k0 + tig + 4]);
            }
            #pragma unroll
            for (int i = 0; i < 2; ++i)
                #pragma unroll
                for (int j = 0; j < 8; ++j)
                    mma_tf32(acc[i][j], af[i][0], af[i][1], af[i][2], af[i][3],
                             bf[j][0], bf[j][1]);
        }
        __syncthreads();
    }
}

// QKV projection: grid (8, 64, 3); scatter to [B,H,T,HS]
__global__ __launch_bounds__(256) void qkv_gemm_kernel(
    const float* __restrict__ x, const float* __restrict__ Wq,
    const float* __restrict__ Wk, const float* __restrict__ Wv)
{
    __shared__ __align__(16) float As[2 * TBM * BKP];
    __shared__ __align__(16) float Ws[2 * TBM * BKP];
    const int z = blockIdx.z;
    const float* W = (z == 0) ? Wq : (z == 1) ? Wk : Wv;
    float* dst     = (z == 0) ? g_q : (z == 1) ? g_k : g_v;
    const int blockM = blockIdx.y * TBM, blockN = blockIdx.x * TBN;

    float acc[2][8][4];
    #pragma unroll
    for (int i = 0; i < 2; ++i)
        #pragma unroll
        for (int j = 0; j < 8; ++j)
            #pragma unroll
            for (int c = 0; c < 4; ++c) acc[i][j][c] = 0.f;

    gemm_tf32_tile(x, W, blockM, blockN, acc, As, Ws);

    const int wid = threadIdx.x >> 5, lane = threadIdx.x & 31;
    const int grp = lane >> 2, tig = lane & 3;
    const int warpM = (wid & 3) * 32, warpN = (wid >> 2) * 64;

    #pragma unroll
    for (int i = 0; i < 2; ++i) {
        #pragma unroll
        for (int j = 0; j < 8; ++j) {
            const int col = blockN + warpN + j*8 + tig*2;
            const int h = col >> 6, d = col & 63;
            #pragma unroll
            for (int rhalf = 0; rhalf < 2; ++rhalf) {
                const int row = blockM + warpM + i*16 + grp + rhalf*8;
                const int b = row >> 10, t = row & (TT-1);
                float2 v2 = make_float2(acc[i][j][rhalf*2], acc[i][j][rhalf*2+1]);
                *(float2*)&dst[((size_t)(b*HH + h)*TT + t)*HSZ + d] = v2;
            }
        }
    }
}

// Output projection: out = att @ Wproj^T
__global__ __launch_bounds__(256) void proj_gemm_kernel(
    const float* __restrict__ Wp, float* __restrict__ out)
{
    __shared__ __align__(16) float As[2 * TBM * BKP];
    __shared__ __align__(16) float Ws[2 * TBM * BKP];
    const int blockM = blockIdx.y * TBM, blockN = blockIdx.x * TBN;

    float acc[2][8][4];
    #pragma unroll
    for (int i = 0; i < 2; ++i)
        #pragma unroll
        for (int j = 0; j < 8; ++j)
            #pragma unroll
            for (int c = 0; c < 4; ++c) acc[i][j][c] = 0.f;

    gemm_tf32_tile(g_att, Wp, blockM, blockN, acc, As, Ws);

    const int wid = threadIdx.x >> 5, lane = threadIdx.x & 31;
    const int grp = lane >> 2, tig = lane & 3;
    const int warpM = (wid & 3) * 32, warpN = (wid >> 2) * 64;

    #pragma unroll
    for (int i = 0; i < 2; ++i) {
        #pragma unroll
        for (int j = 0; j < 8; ++j) {
            const int col = blockN + warpN + j*8 + tig*2;
            #pragma unroll
            for (int rhalf = 0; rhalf < 2; ++rhalf) {
                const int row = blockM + warpM + i*16 + grp + rhalf*8;
                float2 v2 = make_float2(acc[i][j][rhalf*2], acc[i][j][rhalf*2+1]);
                *(float2*)&out[(size_t)row*EE + col] = v2;
            }
        }
    }
}

// ---------------------------------------------------------------------------
// Causal flash attention, fp32 (unchanged from R0).
// ---------------------------------------------------------------------------
#define ALD 68   // 64 + 4 pad

__global__ __launch_bounds__(256) void attn_kernel_f32()
{
    extern __shared__ __align__(16) float sm[];
    float* Qst = sm;               // [64][ALD]  Qst[d][row]
    float* KP  = sm + 64*ALD;      // Kst[d][col]  then  Pst[c][row]
    float* Vs  = sm + 2*64*ALD;    // Vs[c][d]

    const int qb = blockIdx.x, h = blockIdx.y, b = blockIdx.z;
    const float* qp = g_q + ((size_t)(b*HH + h)*TT + qb*64)*HSZ;
    const float* kp = g_k + ((size_t)(b*HH + h)*TT)*HSZ;
    const float* vp = g_v + ((size_t)(b*HH + h)*TT)*HSZ;

    const int tid = threadIdx.x;
    const int tx = tid & 15, ty = tid >> 4;
    const int lr  = tid >> 2;          // 0..63
    const int ld0 = (tid & 3) * 16;    // 0,16,32,48

    #pragma unroll
    for (int u = 0; u < 4; ++u) {
        float4 f = *(const float4*)(qp + (size_t)lr*HSZ + ld0 + u*4);
        Qst[(ld0+u*4+0)*ALD + lr] = f.x;
        Qst[(ld0+u*4+1)*ALD + lr] = f.y;
        Qst[(ld0+u*4+2)*ALD + lr] = f.z;
        Qst[(ld0+u*4+3)*ALD + lr] = f.w;
    }

    float m[4], l[4], o[4][4];
    #pragma unroll
    for (int i = 0; i < 4; ++i) {
        m[i] = -1e30f; l[i] = 0.f;
        #pragma unroll
        for (int j = 0; j < 4; ++j) o[i][j] = 0.f;
    }

    const float scl = 0.125f;  // HS^-0.5

    for (int kb = 0; kb <= qb; ++kb) {
        #pragma unroll
        for (int u = 0; u < 4; ++u) {
            float4 f = *(const float4*)(kp + (size_t)(kb*64 + lr)*HSZ + ld0 + u*4);
            KP[(ld0+u*4+0)*ALD + lr] = f.x;
            KP[(ld0+u*4+1)*ALD + lr] = f.y;
            KP[(ld0+u*4+2)*ALD + lr] = f.z;
            KP[(ld0+u*4+3)*ALD + lr] = f.w;
            float4 g = *(const float4*)(vp + (size_t)(kb*64 + lr)*HSZ + ld0 + u*4);
            *(float4*)&Vs[lr*ALD + ld0 + u*4] = g;
        }
        __syncthreads();

        float s[4][4];
        #pragma unroll
        for (int i = 0; i < 4; ++i)
            #pragma unroll
            for (int j = 0; j < 4; ++j) s[i][j] = 0.f;

        #pragma unroll 8
        for (int d = 0; d < 64; ++d) {
            float4 qv = *(const float4*)&Qst[d*ALD + ty*4];
            float4 kv = *(const float4*)&KP [d*ALD + tx*4];
            float qa[4] = {qv.x, qv.y, qv.z, qv.w};
            float ka[4] = {kv.x, kv.y, kv.z, kv.w};
            #pragma unroll
            for (int i = 0; i < 4; ++i)
                #pragma unroll
                for (int j = 0; j < 4; ++j)
                    s[i][j] += qa[i] * ka[j];
        }

        #pragma unroll
        for (int i = 0; i < 4; ++i)
            #pragma unroll
            for (int j = 0; j < 4; ++j) s[i][j] *= scl;
        if (kb == qb) {
            #pragma unroll
            for (int i = 0; i < 4; ++i)
                #pragma unroll
                for (int j = 0; j < 4; ++j)
                    if (tx*4 + j > ty*4 + i) s[i][j] = -1e30f;
        }

        float alpha[4];
        #pragma unroll
        for (int i = 0; i < 4; ++i) {
            float rm = fmaxf(fmaxf(s[i][0], s[i][1]), fmaxf(s[i][2], s[i][3]));
            rm = fmaxf(rm, __shfl_xor_sync(0xffffffffu, rm, 8));
            rm = fmaxf(rm, __shfl_xor_sync(0xffffffffu, rm, 4));
            rm = fmaxf(rm, __shfl_xor_sync(0xffffffffu, rm, 2));
            rm = fmaxf(rm, __shfl_xor_sync(0xffffffffu, rm, 1));
            const float mn = fmaxf(m[i], rm);
            alpha[i] = __expf(m[i] - mn);
            m[i] = mn;
            float rs = 0.f;
            #pragma unroll
            for (int j = 0; j < 4; ++j) { s[i][j] = __expf(s[i][j] - mn); rs += s[i][j]; }
            rs += __shfl_xor_sync(0xffffffffu, rs, 8);
            rs += __shfl_xor_sync(0xffffffffu, rs, 4);
            rs += __shfl_xor_sync(0xffffffffu, rs, 2);
            rs += __shfl_xor_sync(0xffffffffu, rs, 1);
            l[i] = l[i]*alpha[i] + rs;
            #pragma unroll
            for (int j = 0; j < 4; ++j) o[i][j] *= alpha[i];
        }

        __syncthreads();
        #pragma unroll
        for (int j = 0; j < 4; ++j)
            #pragma unroll
            for (int i = 0; i < 4; ++i)
                KP[(tx*4+j)*ALD + ty*4 + i] = s[i][j];
        __syncthreads();

        #pragma unroll 8
        for (int c = 0; c < 64; ++c) {
            float4 pv = *(const float4*)&KP[c*ALD + ty*4];
            float4 vv = *(const float4*)&Vs[c*ALD + tx*4];
            float pa[4] = {pv.x, pv.y, pv.z, pv.w};
            float va[4] = {vv.x, vv.y, vv.z, vv.w};
            #pragma unroll
            for (int i = 0; i < 4; ++i)
                #pragma unroll
                for (int j = 0; j < 4; ++j)
                    o[i][j] += pa[i] * va[j];
        }
        __syncthreads();
    }

    float* ap = g_att + ((size_t)b*TT + qb*64)*EE + h*HSZ;
    #pragma unroll
    for (int i = 0; i < 4; ++i) {
        const float inv = 1.0f / l[i];
        float4 v4 = make_float4(o[i][0]*inv, o[i][1]*inv, o[i][2]*inv, o[i][3]*inv);
        *(float4*)&ap[(size_t)(ty*4+i)*EE + tx*4] = v4;
    }
}

// ---------------------------------------------------------------------------
extern "C" void kernel_launch(void* const* d_in, const int* in_sizes, int n_in,
                              void* d_out, int out_size)
{
    const float* x  = (const float*)d_in[0];
    const float* Wk = (const float*)d_in[1];
    const float* Wq = (const float*)d_in[2];
    const float* Wv = (const float*)d_in[3];
    const float* Wp = (const float*)d_in[4];
    float* out = (float*)d_out;

    const int attn_smem = 3 * 64 * ALD * (int)sizeof(float);   // 52224 B
    cudaFuncSetAttribute(attn_kernel_f32,
                         cudaFuncAttributeMaxDynamicSharedMemorySize, attn_smem);

    dim3 gq(EE/TBN, MTOT/TBM, 3);          // (8, 64, 3)
    qkv_gemm_kernel<<<gq, 256>>>(x, Wq, Wk, Wv);

    dim3 ga(TT/64, HH, BB);                // (16, 16, 8)
    attn_kernel_f32<<<ga, 256, attn_smem>>>();

    dim3 gp(EE/TBN, MTOT/TBM);             // (8, 64)
    proj_gemm_kernel<<<gp, 256>>>(Wp, out);
}

// round 4
// speedup vs baseline: 2.2638x; 2.0715x over previous
// R3: (a) GEMMs: 2 CTAs/SM + k-permuted smem -> LDS.64 fragment loads.
//     (b) Attention rewritten with mma.sync tf32 (m16n8k8) + online softmax.
#include <cuda_runtime.h>

#define BB  8
#define TT  1024
#define EE  1024
#define HH  16
#define HSZ 64
#define MTOT (BB*TT)   // 8192

__device__ __align__(16) float g_q[BB*HH*TT*HSZ];
__device__ __align__(16) float g_k[BB*HH*TT*HSZ];
__device__ __align__(16) float g_v[BB*HH*TT*HSZ];
__device__ __align__(16) float g_att[BB*TT*EE];

__device__ __forceinline__ unsigned f2tf32(float f) {
    unsigned r; asm("cvt.rna.tf32.f32 %0, %1;" : "=r"(r) : "f"(f));
    return r;
}

__device__ __forceinline__ void mma_tf32(float c[4],
    unsigned a0, unsigned a1, unsigned a2, unsigned a3,
    unsigned b0, unsigned b1)
{
    asm volatile(
        "mma.sync.aligned.m16n8k8.row.col.f32.tf32.tf32.f32 "
        "{%0,%1,%2,%3}, {%4,%5,%6,%7}, {%8,%9}, {%0,%1,%2,%3};"
        : "+f"(c[0]), "+f"(c[1]), "+f"(c[2]), "+f"(c[3])
        : "r"(a0), "r"(a1), "r"(a2), "r"(a3), "r"(b0), "r"(b1));
}

// logical k -> physical float offset: pairs (k, k+4) land adjacent (8B) so
// fragment loads are single LDS.64. Works for any k width multiple of 8.
__device__ __forceinline__ int kperm(int k) {
    return ((k >> 3) << 3) | ((k & 3) << 1) | ((k >> 2) & 1);
}

// ---------------------------------------------------------------------------
// TF32 GEMM: C = A @ W^T. 128x128 tile, BK=16, 256 thr = 8 warps (4m x 2n),
// double-buffered smem, LDw=24 floats (16 data + 8 pad; 12*grp+tig mod 16
// bijective -> conflict-free LDS.64 fragment loads).
// ---------------------------------------------------------------------------
#define TBM 128
#define TBN 128
#define TBK 16
#define LDW 24

__device__ __forceinline__ void gemm_tf32_tile(
    const float* __restrict__ A, const float* __restrict__ W,
    int blockM, int blockN, float acc[2][8][4],
    float* As, float* Ws)   // each [2][128*LDW]
{
    const int tid  = threadIdx.x;
    const int wid  = tid >> 5;
    const int lane = tid & 31;
    const int grp  = lane >> 2;
    const int tig  = lane & 3;
    const int warpM = (wid & 3) * 32;
    const int warpN = (wid >> 2) * 64;

    const int r0 = tid >> 2;
    const int r1 = r0 + 64;
    const int cg = (tid & 3) * 4;   // k group 0,4,8,12 (one perm slab each)
    const float* Ap0 = A + (size_t)(blockM + r0) * EE + cg;
    const float* Ap1 = A + (size_t)(blockM + r1) * EE + cg;
    const float* Wp0 = W + (size_t)(blockN + r0) * EE + cg;
    const float* Wp1 = W + (size_t)(blockN + r1) * EE + cg;

    float4 fa0 = *(const float4*)Ap0;
    float4 fa1 = *(const float4*)Ap1;
    float4 fw0 = *(const float4*)Wp0;
    float4 fw1 = *(const float4*)Wp1;

    const int NKT = EE / TBK;   // 64

    #pragma unroll 1
    for (int kt = 0; kt < NKT; ++kt) {
        float* as = As + (kt & 1) * (TBM * LDW);
        float* ws = Ws + (kt & 1) * (TBM * LDW);

        const float* pa0 = &fa0.x; const float* pa1 = &fa1.x;
        const float* pw0 = &fw0.x; const float* pw1 = &fw1.x;
        #pragma unroll
        for (int u = 0; u < 4; ++u) {
            const int kp = kperm(cg + u);
            as[r0*LDW + kp] = __uint_as_float(f2tf32(pa0[u]));
            as[r1*LDW + kp] = __uint_as_float(f2tf32(pa1[u]));
            ws[r0*LDW + kp] = __uint_as_float(f2tf32(pw0[u]));
            ws[r1*LDW + kp] = __uint_as_float(f2tf32(pw1[u]));
        }
        __syncthreads();

        if (kt + 1 < NKT) {
            const int ko = (kt + 1) * TBK;
            fa0 = *(const float4*)(Ap0 + ko);
            fa1 = *(const float4*)(Ap1 + ko);
            fw0 = *(const float4*)(Wp0 + ko);
            fw1 = *(const float4*)(Wp1 + ko);
        }

        #pragma unroll
        for (int ks = 0; ks < 2; ++ks) {
            const int koff = ks * 8 + 2 * tig;
            float2 a02[2], a13[2];
            #pragma unroll
            for (int i = 0; i < 2; ++i) {
                const int rb = warpM + i * 16;
                a02[i] = *(const float2*)&as[(rb + grp    ) * LDW + koff];
                a13[i] = *(const float2*)&as[(rb + grp + 8) * LDW + koff];
            }
            #pragma unroll
            for (int j = 0; j < 8; ++j) {
                float2 b01 = *(const float2*)&ws[(warpN + j*8 + grp) * LDW + koff];
                #pragma unroll
                for (int i = 0; i < 2; ++i)
                    mma_tf32(acc[i][j],
                        __float_as_uint(a02[i].x), __float_as_uint(a13[i].x),
                        __float_as_uint(a02[i].y), __float_as_uint(a13[i].y),
                        __float_as_uint(b01.x),    __float_as_uint(b01.y));
            }
        }
        __syncthreads();
    }
}

__global__ __launch_bounds__(256, 2) void qkv_gemm_kernel(
    const float* __restrict__ x, const float* __restrict__ Wq,
    const float* __restrict__ Wk, const float* __restrict__ Wv)
{
    __shared__ __align__(16) float As[2 * TBM * LDW];
    __shared__ __align__(16) float Ws[2 * TBM * LDW];
    const int z = blockIdx.z;
    const float* W = (z == 0) ? Wq : (z == 1) ? Wk : Wv;
    float* dst     = (z == 0) ? g_q : (z == 1) ? g_k : g_v;
    const int blockM = blockIdx.y * TBM, blockN = blockIdx.x * TBN;

    float acc[2][8][4];
    #pragma unroll
    for (int i = 0; i < 2; ++i)
        #pragma unroll
        for (int j = 0; j < 8; ++j)
            #pragma unroll
            for (int c = 0; c < 4; ++c) acc[i][j][c] = 0.f;

    gemm_tf32_tile(x, W, blockM, blockN, acc, As, Ws);

    const int wid = threadIdx.x >> 5, lane = threadIdx.x & 31;
    const int grp = lane >> 2, tig = lane & 3;
    const int warpM = (wid & 3) * 32, warpN = (wid >> 2) * 64;

    #pragma unroll
    for (int i = 0; i < 2; ++i) {
        #pragma unroll
        for (int j = 0; j < 8; ++j) {
            const int col = blockN + warpN + j*8 + tig*2;
            const int h = col >> 6, d = col & 63;
            #pragma unroll
            for (int rh = 0; rh < 2; ++rh) {
                const int row = blockM + warpM + i*16 + grp + rh*8;
                const int b = row >> 10, t = row & (TT-1);
                float2 v2 = make_float2(acc[i][j][rh*2], acc[i][j][rh*2+1]);
                *(float2*)&dst[((size_t)(b*HH + h)*TT + t)*HSZ + d] = v2;
            }
        }
    }
}

__global__ __launch_bounds__(256, 2) void proj_gemm_kernel(
    const float* __restrict__ Wp, float* __restrict__ out)
{
    __shared__ __align__(16) float As[2 * TBM * LDW];
    __shared__ __align__(16) float Ws[2 * TBM * LDW];
    const int blockM = blockIdx.y * TBM, blockN = blockIdx.x * TBN;

    float acc[2][8][4];
    #pragma unroll
    for (int i = 0; i < 2; ++i)
        #pragma unroll
        for (int j = 0; j < 8; ++j)
            #pragma unroll
            for (int c = 0; c < 4; ++c) acc[i][j][c] = 0.f;

    gemm_tf32_tile(g_att, Wp, blockM, blockN, acc, As, Ws);

    const int wid = threadIdx.x >> 5, lane = threadIdx.x & 31;
    const int grp = lane >> 2, tig = lane & 3;
    const int warpM = (wid & 3) * 32, warpN = (wid >> 2) * 64;

    #pragma unroll
    for (int i = 0; i < 2; ++i) {
        #pragma unroll
        for (int j = 0; j < 8; ++j) {
            const int col = blockN + warpN + j*8 + tig*2;
            #pragma unroll
            for (int rh = 0; rh < 2; ++rh) {
                const int row = blockM + warpM + i*16 + grp + rh*8;
                float2 v2 = make_float2(acc[i][j][rh*2], acc[i][j][rh*2+1]);
                *(float2*)&out[(size_t)row*EE + col] = v2;
            }
        }
    }
}

// ---------------------------------------------------------------------------
// Causal flash attention with mma.sync tf32.
// CTA: 128 q-rows of one (b,h). 8 warps x 16 q-rows. KV tiles of 64 cols.
// smem (dynamic, 110592B): Qs[128][72], Ks[64][72], Vs[64][72] ([d][s]),
// Ps[128][72]. All in kperm layout; ALDW=72 -> conflict-free LDS.64
// (36 mod 16 = 4; 4*grp+tig bijective over half-warp).
// ---------------------------------------------------------------------------
#define ALDW 72

__global__ __launch_bounds__(256, 2) void attn_mma_kernel()
{
    extern __shared__ __align__(16) float sm[];
    float* Qs = sm;                  // [128][ALDW]
    float* Ks = Qs + 128*ALDW;       // [64][ALDW]   Ks[s][d-perm]
    float* Vs = Ks + 64*ALDW;        // [64][ALDW]   Vs[d][s-perm]
    float* Ps = Vs + 64*ALDW;        // [128][ALDW]  Ps[r][s-perm]

    const int qb = blockIdx.x, h = blockIdx.y, b = blockIdx.z;
    const float* qp = g_q + ((size_t)(b*HH + h)*TT + qb*128)*HSZ;
    const float* kp = g_k + ((size_t)(b*HH + h)*TT)*HSZ;
    const float* vp = g_v + ((size_t)(b*HH + h)*TT)*HSZ;

    const int tid  = threadIdx.x;
    const int wid  = tid >> 5;
    const int lane = tid & 31;
    const int grp  = lane >> 2;
    const int tig  = lane & 3;
    const int wm   = wid * 16;       // warp's q-row base within tile

    // stage Q (pre-scaled by HS^-0.5 = 0.125, exact power of 2; tf32 convert)
    {
        const int row = tid >> 1;
        const int d0  = (tid & 1) * 32;
        #pragma unroll
        for (int u = 0; u < 8; ++u) {
            float4 f = *(const float4*)(qp + (size_t)row*HSZ + d0 + u*4);
            const float* pf = &f.x;
            #pragma unroll
            for (int w = 0; w < 4; ++w)
                Qs[row*ALDW + kperm(d0 + u*4 + w)] =
                    __uint_as_float(f2tf32(pf[w] * 0.125f));
        }
    }

    float m[2], l[2], o[8][4];
    m[0] = m[1] = -1e30f; l[0] = l[1] = 0.f;
    #pragma unroll
    for (int j = 0; j < 8; ++j)
        #pragma unroll
        for (int c = 0; c < 4; ++c) o[j][c] = 0.f;

    const int ntiles = 2*qb + 2;

    for (int kt = 0; kt < ntiles; ++kt) {
        // stage K tile [s][d-perm] and V tile [d][s-perm]
        {
            const int s  = tid >> 2;
            const int d0 = (tid & 3) * 16;
            const int sp = kperm(s);
            #pragma unroll
            for (int u = 0; u < 4; ++u) {
                float4 f = *(const float4*)(kp + (size_t)(kt*64 + s)*HSZ + d0 + u*4);
                float4 g = *(const float4*)(vp + (size_t)(kt*64 + s)*HSZ + d0 + u*4);
                const float* pf = &f.x; const float* pg = &g.x;
                #pragma unroll
                for (int w = 0; w < 4; ++w) {
                    Ks[s*ALDW + kperm(d0 + u*4 + w)] = __uint_as_float(f2tf32(pf[w]));
                    Vs[(d0 + u*4 + w)*ALDW + sp]     = __uint_as_float(f2tf32(pg[w]));
                }
            }
        }
        __syncthreads();

        // S = Q K^T  (warp: 16 x 64 -> 8 n-tiles, 8 d-chunks)
        float sacc[8][4];
        #pragma unroll
        for (int j = 0; j < 8; ++j)
            #pragma unroll
            for (int c = 0; c < 4; ++c) sacc[j][c] = 0.f;

        #pragma unroll
        for (int kc = 0; kc < 8; ++kc) {
            const int koff = kc*8 + 2*tig;
            float2 a02 = *(const float2*)&Qs[(wm + grp    )*ALDW + koff];
            float2 a13 = *(const float2*)&Qs[(wm + grp + 8)*ALDW + koff];
            #pragma unroll
            for (int j = 0; j < 8; ++j) {
                float2 b01 = *(const float2*)&Ks[(j*8 + grp)*ALDW + koff];
                mma_tf32(sacc[j],
                    __float_as_uint(a02.x), __float_as_uint(a13.x),
                    __float_as_uint(a02.y), __float_as_uint(a13.y),
                    __float_as_uint(b01.x), __float_as_uint(b01.y));
            }
        }

        // causal mask for diagonal-straddling tiles
        if (kt >= 2*qb) {
            #pragma unroll
            for (int j = 0; j < 8; ++j)
                #pragma unroll
                for (int c = 0; c < 4; ++c) {
                    const int row = qb*128 + wm + grp + (c >> 1)*8;
                    const int col = kt*64 + j*8 + 2*tig + (c & 1);
                    if (col > row) sacc[j][c] = -1e30f;
                }
        }

        // online softmax update (rows grp / grp+8 per thread)
        float alpha[2];
        #pragma unroll
        for (int rh = 0; rh < 2; ++rh) {
            float rm = -1e30f;
            #pragma unroll
            for (int j = 0; j < 8; ++j)
                rm = fmaxf(rm, fmaxf(sacc[j][rh*2], sacc[j][rh*2+1]));
            rm = fmaxf(rm, __shfl_xor_sync(0xffffffffu, rm, 1));
            rm = fmaxf(rm, __shfl_xor_sync(0xffffffffu, rm, 2));
            const float mn = fmaxf(m[rh], rm);
            alpha[rh] = __expf(m[rh] - mn);
            m[rh] = mn;
            float rs = 0.f;
            #pragma unroll
            for (int j = 0; j < 8; ++j) {
                float p0 = __expf(sacc[j][rh*2  ] - mn);
                float p1 = __expf(sacc[j][rh*2+1] - mn);
                sacc[j][rh*2] = p0; sacc[j][rh*2+1] = p1;
                rs += p0 + p1;
            }
            rs += __shfl_xor_sync(0xffffffffu, rs, 1);
            rs += __shfl_xor_sync(0xffffffffu, rs, 2);
            l[rh] = l[rh]*alpha[rh] + rs;
            #pragma unroll
            for (int j = 0; j < 8; ++j) {
                o[j][rh*2]   *= alpha[rh];
                o[j][rh*2+1] *= alpha[rh];
            }
        }

        // P -> smem (tf32, perm layout)
        #pragma unroll
        for (int j = 0; j < 8; ++j) {
            const int p0 = kperm(j*8 + 2*tig);
            const int p1 = kperm(j*8 + 2*tig + 1);
            #pragma unroll
            for (int rh = 0; rh < 2; ++rh) {
                const int row = wm + grp + rh*8;
                Ps[row*ALDW + p0] = __uint_as_float(f2tf32(sacc[j][rh*2]));
                Ps[row*ALDW + p1] = __uint_as_float(f2tf32(sacc[j][rh*2+1]));
            }
        }
        __syncthreads();

        // O += P V  (k dim = s, 8 chunks; B operand = Vs[d][s-perm])
        #pragma unroll
        for (int ss = 0; ss < 8; ++ss) {
            const int koff = ss*8 + 2*tig;
            float2 a02 = *(const float2*)&Ps[(wm + grp    )*ALDW + koff];
            float2 a13 = *(const float2*)&Ps[(wm + grp + 8)*ALDW + koff];
            #pragma unroll
            for (int j = 0; j < 8; ++j) {
                float2 b01 = *(const float2*)&Vs[(j*8 + grp)*ALDW + koff];
                mma_tf32(o[j],
                    __float_as_uint(a02.x), __float_as_uint(a13.x),
                    __float_as_uint(a02.y), __float_as_uint(a13.y),
                    __float_as_uint(b01.x), __float_as_uint(b01.y));
            }
        }
        __syncthreads();   // V/K/P reads done before next tile overwrites
    }

    // normalize + store (head-concat layout)
    const float inv0 = 1.0f / l[0];
    const float inv1 = 1.0f / l[1];
    #pragma unroll
    for (int j = 0; j < 8; ++j) {
        const int col = h*HSZ + j*8 + 2*tig;
        #pragma unroll
        for (int rh = 0; rh < 2; ++rh) {
            const float inv = rh ? inv1 : inv0;
            const int row = qb*128 + wm + grp + rh*8;
            float2 v2 = make_float2(o[j][rh*2]*inv, o[j][rh*2+1]*inv);
            *(float2*)&g_att[((size_t)b*TT + row)*EE + col] = v2;
        }
    }
}

// ---------------------------------------------------------------------------
extern "C" void kernel_launch(void* const* d_in, const int* in_sizes, int n_in,
                              void* d_out, int out_size)
{
    const float* x  = (const float*)d_in[0];
    const float* Wk = (const float*)d_in[1];
    const float* Wq = (const float*)d_in[2];
    const float* Wv = (const float*)d_in[3];
    const float* Wp = (const float*)d_in[4];
    float* out = (float*)d_out;

    const int attn_smem = (128 + 64 + 64 + 128) * ALDW * (int)sizeof(float); // 110592
    cudaFuncSetAttribute(attn_mma_kernel,
                         cudaFuncAttributeMaxDynamicSharedMemorySize, attn_smem);

    dim3 gq(EE/TBN, MTOT/TBM, 3);          // (8, 64, 3)
    qkv_gemm_kernel<<<gq, 256>>>(x, Wq, Wk, Wv);

    dim3 ga(TT/128, HH, BB);               // (8, 16, 8)
    attn_mma_kernel<<<ga, 256, attn_smem>>>();

    dim3 gp(EE/TBN, MTOT/TBM);             // (8, 64)
    proj_gemm_kernel<<<gp, 256>>>(Wp, out);
}

// round 6
// speedup vs baseline: 3.0603x; 1.3518x over previous
// R5: tcgen05 unavailable (harness PTX target = compute_103, no 'a').
// GEMMs stay mma.sync tf32 but: (1) k-adjacency remap kills the kperm
// scatter, (2) operands pre-rounded to tf32 -> staging is pure cp.async,
// (3) 2 CTAs/SM. Attention: same algorithm, vectorized staging.
#include <cuda_runtime.h>
#include <stdint.h>

#define BB  8
#define TT  1024
#define EE  1024
#define HH  16
#define HSZ 64
#define MTOT (BB*TT)   // 8192
#define XN  ((size_t)MTOT*EE)
#define WN  ((size_t)EE*EE)

__device__ __align__(16) float g_q[(size_t)BB*HH*TT*HSZ];
__device__ __align__(16) float g_k[(size_t)BB*HH*TT*HSZ];
__device__ __align__(16) float g_v[(size_t)BB*HH*TT*HSZ];
__device__ __align__(16) float g_att[XN];    // tf32-rounded attention output
__device__ __align__(16) float g_xt[XN];     // tf32-rounded x
__device__ __align__(16) float g_wt[4*WN];   // tf32-rounded [Wq|Wk|Wv|Wp]

__device__ __forceinline__ unsigned f2tf32(float f) {
    unsigned r; asm("cvt.rna.tf32.f32 %0, %1;" : "=r"(r) : "f"(f));
    return r;
}
__device__ __forceinline__ void mma_tf32(float c[4],
    unsigned a0, unsigned a1, unsigned a2, unsigned a3,
    unsigned b0, unsigned b1)
{
    asm volatile(
        "mma.sync.aligned.m16n8k8.row.col.f32.tf32.tf32.f32 "
        "{%0,%1,%2,%3}, {%4,%5,%6,%7}, {%8,%9}, {%0,%1,%2,%3};"
        : "+f"(c[0]), "+f"(c[1]), "+f"(c[2]), "+f"(c[3])
        : "r"(a0), "r"(a1), "r"(a2), "r"(a3), "r"(b0), "r"(b1));
}
__device__ __forceinline__ uint32_t s2u(const void* p) {
    uint32_t a;
    asm("{ .reg .u64 t; cvta.to.shared.u64 t, %1; cvt.u32.u64 %0, t; }"
        : "=r"(a) : "l"(p));
    return a;
}
__device__ __forceinline__ void cpa16(uint32_t dst, const void* src) {
    asm volatile("cp.async.cg.shared.global [%0], [%1], 16;"
                 :: "r"(dst), "l"(src) : "memory");
}
#define CP_COMMIT() asm volatile("cp.async.commit_group;" ::: "memory")
#define CP_WAIT1()  asm volatile("cp.async.wait_group 1;" ::: "memory")

// ---------------------------------------------------------------------------
// prepass: round x and the 4 weight matrices to tf32 precision (f32 storage)
// ---------------------------------------------------------------------------
__global__ __launch_bounds__(256) void round_tf32_kernel(
    const float* __restrict__ x,  const float* __restrict__ wq,
    const float* __restrict__ wk, const float* __restrict__ wv,
    const float* __restrict__ wp)
{
    const size_t i4 = (size_t)blockIdx.x * blockDim.x + threadIdx.x;
    const size_t e  = i4 * 4;
    if (e >= XN + 4 * WN) return;

    const float* src; float* dst; size_t off;
    if (e < XN) { src = x; dst = g_xt; off = e; }
    else {
        const size_t we = e - XN;
        const int z = (int)(we / WN);
        off = we - (size_t)z * WN;
        src = (z == 0) ? wq : (z == 1) ? wk : (z == 2) ? wv : wp;
        dst = g_wt + (size_t)z * WN;
    }
    float4 v = *(const float4*)(src + off);
    v.x = __uint_as_float(f2tf32(v.x));
    v.y = __uint_as_float(f2tf32(v.y));
    v.z = __uint_as_float(f2tf32(v.z));
    v.w = __uint_as_float(f2tf32(v.w));
    *(float4*)(dst + off) = v;
}

// ---------------------------------------------------------------------------
// TF32 GEMM: C = A @ W^T, operands pre-rounded. 128x128 tile, BK=16,
// 8 warps (4m x 2n), warp tile 32x64. cp.async double-buffered staging,
// contiguous smem rows (LDW=24 pad), k-adjacency fragment mapping
// (k in {2*tig, 2*tig+1} for both operands) -> all frag loads LDS.64.
// ---------------------------------------------------------------------------
#define LDW   24
#define TILEF (128*LDW)              // 3072 floats per matrix tile
#define GSMEM (2*2*TILEF*4)          // 49152 B

__device__ __forceinline__ void gemm_stage(
    uint32_t sbuf, const float* __restrict__ A, const float* __restrict__ W,
    int c)
{
    const int tid = threadIdx.x;
    // 1024 16B-chunks: [matrix(2)][row(128)][chunk(4)]
    #pragma unroll
    for (int u = 0; u < 4; ++u) {
        const int i   = tid + u * 256;
        const int mat = i >> 9;
        const int j   = i & 511;
        const int row = j >> 2;
        const int cq  = (j & 3) * 4;
        const float* src = (mat ? W : A) + (size_t)row * EE + c * 16 + cq;
        const uint32_t dst = sbuf + (uint32_t)(mat * TILEF + row * LDW + cq) * 4;
        cpa16(dst, src);
    }
}

__device__ __forceinline__ void gemm_core(
    const float* __restrict__ A, const float* __restrict__ W,
    float acc[2][8][4], float* sm)
{
    const int tid  = threadIdx.x;
    const int wid  = tid >> 5;
    const int lane = tid & 31;
    const int grp  = lane >> 2;
    const int tig  = lane & 3;
    const int warpM = (wid & 3) * 32;
    const int warpN = (wid >> 2) * 64;
    const uint32_t sb = s2u(sm);

    gemm_stage(sb, A, W, 0); CP_COMMIT();
    gemm_stage(sb + 2 * TILEF * 4, A, W, 1); CP_COMMIT();

    #pragma unroll 1
    for (int c = 0; c < EE / 16; ++c) {
        CP_WAIT1();
        __syncthreads();
        const float* as = sm + (c & 1) * 2 * TILEF;
        const float* ws = as + TILEF;

        #pragma unroll
        for (int ks = 0; ks < 2; ++ks) {
            const int koff = ks * 8 + 2 * tig;
            float2 a02[2], a13[2];
            #pragma unroll
            for (int i = 0; i < 2; ++i) {
                const int rb = warpM + i * 16;
                a02[i] = *(const float2*)&as[(rb + grp    ) * LDW + koff];
                a13[i] = *(const float2*)&as[(rb + grp + 8) * LDW + koff];
            }
            #pragma unroll
            for (int j = 0; j < 8; ++j) {
                float2 b01 = *(const float2*)&ws[(warpN + j*8 + grp) * LDW + koff];
                #pragma unroll
                for (int i = 0; i < 2; ++i)
                    mma_tf32(acc[i][j],
                        __float_as_uint(a02[i].x), __float_as_uint(a13[i].x),
                        __float_as_uint(a02[i].y), __float_as_uint(a13[i].y),
                        __float_as_uint(b01.x),    __float_as_uint(b01.y));
            }
        }
        __syncthreads();
        if (c + 2 < EE / 16)
            gemm_stage(sb + (c & 1) * 2 * TILEF * 4, A, W, c + 2);
        CP_COMMIT();
    }
}

__global__ __launch_bounds__(256, 2) void qkv_gemm_kernel()
{
    extern __shared__ __align__(16) float sm[];
    const int z = blockIdx.z;
    const int blockM = blockIdx.y * 128, blockN = blockIdx.x * 128;

    float acc[2][8][4];
    #pragma unroll
    for (int i = 0; i < 2; ++i)
        #pragma unroll
        for (int j = 0; j < 8; ++j)
            #pragma unroll
            for (int c = 0; c < 4; ++c) acc[i][j][c] = 0.f;

    gemm_core(g_xt + (size_t)blockM * EE,
              g_wt + (size_t)z * WN + (size_t)blockN * EE, acc, sm);

    float* dst = (z == 0) ? g_q : (z == 1) ? g_k : g_v;
    const int wid = threadIdx.x >> 5, lane = threadIdx.x & 31;
    const int grp = lane >> 2, tig = lane & 3;
    const int warpM = (wid & 3) * 32, warpN = (wid >> 2) * 64;

    #pragma unroll
    for (int i = 0; i < 2; ++i) {
        #pragma unroll
        for (int j = 0; j < 8; ++j) {
            const int col = blockN + warpN + j*8 + tig*2;
            const int h = col >> 6, d = col & 63;
            #pragma unroll
            for (int rh = 0; rh < 2; ++rh) {
                const int row = blockM + warpM + i*16 + grp + rh*8;
                const int b = row >> 10, t = row & (TT-1);
                float2 v2 = make_float2(acc[i][j][rh*2], acc[i][j][rh*2+1]);
                *(float2*)&dst[((size_t)(b*HH + h)*TT + t)*HSZ + d] = v2;
            }
        }
    }
}

__global__ __launch_bounds__(256, 2) void proj_gemm_kernel(float* __restrict__ out)
{
    extern __shared__ __align__(16) float sm[];
    const int blockM = blockIdx.y * 128, blockN = blockIdx.x * 128;

    float acc[2][8][4];
    #pragma unroll
    for (int i = 0; i < 2; ++i)
        #pragma unroll
        for (int j = 0; j < 8; ++j)
            #pragma unroll
            for (int c = 0; c < 4; ++c) acc[i][j][c] = 0.f;

    gemm_core(g_att + (size_t)blockM * EE,
              g_wt + 3 * WN + (size_t)blockN * EE, acc, sm);

    const int wid = threadIdx.x >> 5, lane = threadIdx.x & 31;
    const int grp = lane >> 2, tig = lane & 3;
    const int warpM = (wid & 3) * 32, warpN = (wid >> 2) * 64;

    #pragma unroll
    for (int i = 0; i < 2; ++i) {
        #pragma unroll
        for (int j = 0; j < 8; ++j) {
            const int col = blockN + warpN + j*8 + tig*2;
            #pragma unroll
            for (int rh = 0; rh < 2; ++rh) {
                const int row = blockM + warpM + i*16 + grp + rh*8;
                float2 v2 = make_float2(acc[i][j][rh*2], acc[i][j][rh*2+1]);
                *(float2*)&out[(size_t)row*EE + col] = v2;
            }
        }
    }
}

// ---------------------------------------------------------------------------
// Causal flash attention, mma.sync tf32, k-adjacency mapping (no kperm):
// Q/K staged with STS.128, P stored with STS.64. Output rounded to tf32.
// ---------------------------------------------------------------------------
#define ALDW 72

__global__ __launch_bounds__(256, 2) void attn_mma_kernel()
{
    extern __shared__ __align__(16) float sm[];
    float* Qs = sm;                  // [128][ALDW]
    float* Ks = Qs + 128 * ALDW;     // [64][ALDW]
    float* Vs = Ks + 64 * ALDW;      // [64][ALDW]  Vs[d][s]
    float* Ps = Vs + 64 * ALDW;      // [128][ALDW]

    const int qb = blockIdx.x, h = blockIdx.y, b = blockIdx.z;
    const float* qp = g_q + ((size_t)(b * HH + h) * TT + qb * 128) * HSZ;
    const float* kp = g_k + ((size_t)(b * HH + h) * TT) * HSZ;
    const float* vp = g_v + ((size_t)(b * HH + h) * TT) * HSZ;

    const int tid  = threadIdx.x;
    const int wid  = tid >> 5;
    const int lane = tid & 31;
    const int grp  = lane >> 2;
    const int tig  = lane & 3;
    const int wm   = wid * 16;

    // stage Q (pre-scaled by HS^-0.5 = 0.125; tf32-round; contiguous STS.128)
    {
        const int row = tid >> 1;
        const int d0  = (tid & 1) * 32;
        #pragma unroll
        for (int u = 0; u < 8; ++u) {
            float4 f = *(const float4*)(qp + (size_t)row * HSZ + d0 + u * 4);
            f.x = __uint_as_float(f2tf32(f.x * 0.125f));
            f.y = __uint_as_float(f2tf32(f.y * 0.125f));
            f.z = __uint_as_float(f2tf32(f.z * 0.125f));
            f.w = __uint_as_float(f2tf32(f.w * 0.125f));
            *(float4*)&Qs[row * ALDW + d0 + u * 4] = f;
        }
    }

    float m[2], l[2], o[8][4];
    m[0] = m[1] = -1e30f; l[0] = l[1] = 0.f;
    #pragma unroll
    for (int j = 0; j < 8; ++j)
        #pragma unroll
        for (int c = 0; c < 4; ++c) o[j][c] = 0.f;

    const int ntiles = 2 * qb + 2;

    for (int kt = 0; kt < ntiles; ++kt) {
        // stage K [s][d] (STS.128) and V [d][s] (scalar transpose)
        {
            const int s  = tid >> 2;
            const int d0 = (tid & 3) * 16;
            #pragma unroll
            for (int u = 0; u < 4; ++u) {
                float4 f = *(const float4*)(kp + (size_t)(kt * 64 + s) * HSZ + d0 + u * 4);
                f.x = __uint_as_float(f2tf32(f.x));
                f.y = __uint_as_float(f2tf32(f.y));
                f.z = __uint_as_float(f2tf32(f.z));
                f.w = __uint_as_float(f2tf32(f.w));
                *(float4*)&Ks[s * ALDW + d0 + u * 4] = f;
                float4 g = *(const float4*)(vp + (size_t)(kt * 64 + s) * HSZ + d0 + u * 4);
                const float* pg = &g.x;
                #pragma unroll
                for (int w = 0; w < 4; ++w)
                    Vs[(d0 + u * 4 + w) * ALDW + s] = __uint_as_float(f2tf32(pg[w]));
            }
        }
        __syncthreads();

        // S = Q K^T
        float sacc[8][4];
        #pragma unroll
        for (int j = 0; j < 8; ++j)
            #pragma unroll
            for (int c = 0; c < 4; ++c) sacc[j][c] = 0.f;

        #pragma unroll
        for (int kc = 0; kc < 8; ++kc) {
            const int koff = kc * 8 + 2 * tig;
            float2 a02 = *(const float2*)&Qs[(wm + grp    ) * ALDW + koff];
            float2 a13 = *(const float2*)&Qs[(wm + grp + 8) * ALDW + koff];
            #pragma unroll
            for (int j = 0; j < 8; ++j) {
                float2 b01 = *(const float2*)&Ks[(j * 8 + grp) * ALDW + koff];
                mma_tf32(sacc[j],
                    __float_as_uint(a02.x), __float_as_uint(a13.x),
                    __float_as_uint(a02.y), __float_as_uint(a13.y),
                    __float_as_uint(b01.x), __float_as_uint(b01.y));
            }
        }

        if (kt >= 2 * qb) {   // diagonal-straddling: causal mask
            #pragma unroll
            for (int j = 0; j < 8; ++j)
                #pragma unroll
                for (int c = 0; c < 4; ++c) {
                    const int row = qb * 128 + wm + grp + (c >> 1) * 8;
                    const int col = kt * 64 + j * 8 + 2 * tig + (c & 1);
                    if (col > row) sacc[j][c] = -1e30f;
                }
        }

        // online softmax
        float alpha[2];
        #pragma unroll
        for (int rh = 0; rh < 2; ++rh) {
            float rm = -1e30f;
            #pragma unroll
            for (int j = 0; j < 8; ++j)
                rm = fmaxf(rm, fmaxf(sacc[j][rh*2], sacc[j][rh*2+1]));
            rm = fmaxf(rm, __shfl_xor_sync(0xffffffffu, rm, 1));
            rm = fmaxf(rm, __shfl_xor_sync(0xffffffffu, rm, 2));
            const float mn = fmaxf(m[rh], rm);
            alpha[rh] = __expf(m[rh] - mn);
            m[rh] = mn;
            float rs = 0.f;
            #pragma unroll
            for (int j = 0; j < 8; ++j) {
                float p0 = __expf(sacc[j][rh*2  ] - mn);
                float p1 = __expf(sacc[j][rh*2+1] - mn);
                sacc[j][rh*2] = p0; sacc[j][rh*2+1] = p1;
                rs += p0 + p1;
            }
            rs += __shfl_xor_sync(0xffffffffu, rs, 1);
            rs += __shfl_xor_sync(0xffffffffu, rs, 2);
            l[rh] = l[rh] * alpha[rh] + rs;
            #pragma unroll
            for (int j = 0; j < 8; ++j) {
                o[j][rh*2]   *= alpha[rh];
                o[j][rh*2+1] *= alpha[rh];
            }
        }

        __syncthreads();
        // P -> smem (adjacent pair = STS.64)
        #pragma unroll
        for (int j = 0; j < 8; ++j) {
            #pragma unroll
            for (int rh = 0; rh < 2; ++rh) {
                const int row = wm + grp + rh * 8;
                float2 p2 = make_float2(
                    __uint_as_float(f2tf32(sacc[j][rh*2])),
                    __uint_as_float(f2tf32(sacc[j][rh*2+1])));
                *(float2*)&Ps[row * ALDW + j * 8 + 2 * tig] = p2;
            }
        }
        __syncthreads();

        // O += P V
        #pragma unroll
        for (int ss = 0; ss < 8; ++ss) {
            const int koff = ss * 8 + 2 * tig;
            float2 a02 = *(const float2*)&Ps[(wm + grp    ) * ALDW + koff];
            float2 a13 = *(const float2*)&Ps[(wm + grp + 8) * ALDW + koff];
            #pragma unroll
            for (int j = 0; j < 8; ++j) {
                float2 b01 = *(const float2*)&Vs[(j * 8 + grp) * ALDW + koff];
                mma_tf32(o[j],
                    __float_as_uint(a02.x), __float_as_uint(a13.x),
                    __float_as_uint(a02.y), __float_as_uint(a13.y),
                    __float_as_uint(b01.x), __float_as_uint(b01.y));
            }
        }
        __syncthreads();
    }

    // normalize + store tf32-rounded (proj GEMM consumes bits directly)
    const float inv0 = 1.0f / l[0];
    const float inv1 = 1.0f / l[1];
    #pragma unroll
    for (int j = 0; j < 8; ++j) {
        const int col = h * HSZ + j * 8 + 2 * tig;
        #pragma unroll
        for (int rh = 0; rh < 2; ++rh) {
            const float inv = rh ? inv1 : inv0;
            const int row = qb * 128 + wm + grp + rh * 8;
            float2 v2 = make_float2(
                __uint_as_float(f2tf32(o[j][rh*2]   * inv)),
                __uint_as_float(f2tf32(o[j][rh*2+1] * inv)));
            *(float2*)&g_att[((size_t)b * TT + row) * EE + col] = v2;
        }
    }
}

// ---------------------------------------------------------------------------
extern "C" void kernel_launch(void* const* d_in, const int* in_sizes, int n_in,
                              void* d_out, int out_size)
{
    const float* x  = (const float*)d_in[0];
    const float* Wk = (const float*)d_in[1];
    const float* Wq = (const float*)d_in[2];
    const float* Wv = (const float*)d_in[3];
    const float* Wp = (const float*)d_in[4];
    float* out = (float*)d_out;

    cudaFuncSetAttribute(qkv_gemm_kernel,
                         cudaFuncAttributeMaxDynamicSharedMemorySize, GSMEM);
    cudaFuncSetAttribute(proj_gemm_kernel,
                         cudaFuncAttributeMaxDynamicSharedMemorySize, GSMEM);
    const int attn_smem = (128 + 64 + 64 + 128) * ALDW * (int)sizeof(float);
    cudaFuncSetAttribute(attn_mma_kernel,
                         cudaFuncAttributeMaxDynamicSharedMemorySize, attn_smem);

    const size_t total4 = (XN + 4 * WN) / 4;
    round_tf32_kernel<<<(unsigned)((total4 + 255) / 256), 256>>>(x, Wq, Wk, Wv, Wp);

    qkv_gemm_kernel<<<dim3(EE / 128, MTOT / 128, 3), 256, GSMEM>>>();

    attn_mma_kernel<<<dim3(TT / 128, HH, BB), 256, attn_smem>>>();

    proj_gemm_kernel<<<dim3(EE / 128, MTOT / 128), 256, GSMEM>>>(out);
}

// round 8
// speedup vs baseline: 3.4771x; 1.1362x over previous
// R6: GEMM BK=32 (half the barriers), attention: V kept [s][d] (no scalar
// transpose), Q/K/V pre-rounded+scaled in QKV epilogue so attn staging is
// pure cp.async. Arithmetic identical to R5 -> same rel_err expected.
#include <cuda_runtime.h>
#include <stdint.h>

#define BB  8
#define TT  1024
#define EE  1024
#define HH  16
#define HSZ 64
#define MTOT (BB*TT)
#define XN  ((size_t)MTOT*EE)
#define WN  ((size_t)EE*EE)

__device__ __align__(16) float g_q[(size_t)BB*HH*TT*HSZ];   // tf32, pre-scaled
__device__ __align__(16) float g_k[(size_t)BB*HH*TT*HSZ];   // tf32
__device__ __align__(16) float g_v[(size_t)BB*HH*TT*HSZ];   // tf32
__device__ __align__(16) float g_att[XN];    // tf32-rounded attention output
__device__ __align__(16) float g_xt[XN];     // tf32-rounded x
__device__ __align__(16) float g_wt[4*WN];   // tf32-rounded [Wq|Wk|Wv|Wp]

__device__ __forceinline__ unsigned f2tf32(float f) {
    unsigned r; asm("cvt.rna.tf32.f32 %0, %1;" : "=r"(r) : "f"(f));
    return r;
}
__device__ __forceinline__ void mma_tf32(float c[4],
    unsigned a0, unsigned a1, unsigned a2, unsigned a3,
    unsigned b0, unsigned b1)
{
    asm volatile(
        "mma.sync.aligned.m16n8k8.row.col.f32.tf32.tf32.f32 "
        "{%0,%1,%2,%3}, {%4,%5,%6,%7}, {%8,%9}, {%0,%1,%2,%3};"
        : "+f"(c[0]), "+f"(c[1]), "+f"(c[2]), "+f"(c[3])
        : "r"(a0), "r"(a1), "r"(a2), "r"(a3), "r"(b0), "r"(b1));
}
__device__ __forceinline__ uint32_t s2u(const void* p) {
    uint32_t a;
    asm("{ .reg .u64 t; cvta.to.shared.u64 t, %1; cvt.u32.u64 %0, t; }"
        : "=r"(a) : "l"(p));
    return a;
}
__device__ __forceinline__ void cpa16(uint32_t dst, const void* src) {
    asm volatile("cp.async.cg.shared.global [%0], [%1], 16;"
                 :: "r"(dst), "l"(src) : "memory");
}
#define CP_COMMIT() asm volatile("cp.async.commit_group;" ::: "memory")
#define CP_WAIT1()  asm volatile("cp.async.wait_group 1;" ::: "memory")
#define CP_WAIT0()  asm volatile("cp.async.wait_group 0;" ::: "memory")

// ---------------------------------------------------------------------------
// prepass: round x and the 4 weight matrices to tf32 precision
// ---------------------------------------------------------------------------
__global__ __launch_bounds__(256) void round_tf32_kernel(
    const float* __restrict__ x,  const float* __restrict__ wq,
    const float* __restrict__ wk, const float* __restrict__ wv,
    const float* __restrict__ wp)
{
    const size_t i4 = (size_t)blockIdx.x * blockDim.x + threadIdx.x;
    const size_t e  = i4 * 4;
    if (e >= XN + 4 * WN) return;

    const float* src; float* dst; size_t off;
    if (e < XN) { src = x; dst = g_xt; off = e; }
    else {
        const size_t we = e - XN;
        const int z = (int)(we / WN);
        off = we - (size_t)z * WN;
        src = (z == 0) ? wq : (z == 1) ? wk : (z == 2) ? wv : wp;
        dst = g_wt + (size_t)z * WN;
    }
    float4 v = *(const float4*)(src + off);
    v.x = __uint_as_float(f2tf32(v.x));
    v.y = __uint_as_float(f2tf32(v.y));
    v.z = __uint_as_float(f2tf32(v.z));
    v.w = __uint_as_float(f2tf32(v.w));
    *(float4*)(dst + off) = v;
}

// ---------------------------------------------------------------------------
// TF32 GEMM: C = A @ W^T, pre-rounded operands. 128x128 tile, BK=32,
// 8 warps (4m x 2n). cp.async double-buffered. LDW=40 (phase-split
// conflict-free LDS.64 fragments).
// ---------------------------------------------------------------------------
#define LDW   40
#define TILEF (128*LDW)              // 5120 floats
#define GSMEM (2*2*TILEF*4)          // 81920 B

__device__ __forceinline__ void gemm_stage(
    uint32_t sbuf, const float* __restrict__ A, const float* __restrict__ W,
    int c)
{
    const int tid = threadIdx.x;
    // 2048 16B-chunks: [matrix(2)][row(128)][chunk(8)]
    #pragma unroll
    for (int u = 0; u < 8; ++u) {
        const int i   = tid + u * 256;
        const int mat = i >> 10;
        const int j   = i & 1023;
        const int row = j >> 3;
        const int cq  = (j & 7) * 4;
        const float* src = (mat ? W : A) + (size_t)row * EE + c * 32 + cq;
        const uint32_t dst = sbuf + (uint32_t)(mat * TILEF + row * LDW + cq) * 4;
        cpa16(dst, src);
    }
}

__device__ __forceinline__ void gemm_core(
    const float* __restrict__ A, const float* __restrict__ W,
    float acc[2][8][4], float* sm)
{
    const int tid  = threadIdx.x;
    const int wid  = tid >> 5;
    const int lane = tid & 31;
    const int grp  = lane >> 2;
    const int tig  = lane & 3;
    const int warpM = (wid & 3) * 32;
    const int warpN = (wid >> 2) * 64;
    const uint32_t sb = s2u(sm);

    gemm_stage(sb, A, W, 0); CP_COMMIT();
    gemm_stage(sb + 2 * TILEF * 4, A, W, 1); CP_COMMIT();

    const int NKT = EE / 32;   // 32

    #pragma unroll 1
    for (int c = 0; c < NKT; ++c) {
        CP_WAIT1();
        __syncthreads();
        const float* as = sm + (c & 1) * 2 * TILEF;
        const float* ws = as + TILEF;

        #pragma unroll
        for (int ks = 0; ks < 4; ++ks) {
            const int koff = ks * 8 + 2 * tig;
            float2 a02[2], a13[2];
            #pragma unroll
            for (int i = 0; i < 2; ++i) {
                const int rb = warpM + i * 16;
                a02[i] = *(const float2*)&as[(rb + grp    ) * LDW + koff];
                a13[i] = *(const float2*)&as[(rb + grp + 8) * LDW + koff];
            }
            #pragma unroll
            for (int j = 0; j < 8; ++j) {
                float2 b01 = *(const float2*)&ws[(warpN + j*8 + grp) * LDW + koff];
                #pragma unroll
                for (int i = 0; i < 2; ++i)
                    mma_tf32(acc[i][j],
                        __float_as_uint(a02[i].x), __float_as_uint(a13[i].x),
                        __float_as_uint(a02[i].y), __float_as_uint(a13[i].y),
                        __float_as_uint(b01.x),    __float_as_uint(b01.y));
            }
        }
        __syncthreads();
        if (c + 2 < NKT)
            gemm_stage(sb + (c & 1) * 2 * TILEF * 4, A, W, c + 2);
        CP_COMMIT();
    }
}

// QKV: epilogue writes tf32-rounded q/k/v, q pre-scaled by HS^-0.5 = 0.125.
__global__ __launch_bounds__(256, 2) void qkv_gemm_kernel()
{
    extern __shared__ __align__(16) float sm[];
    const int z = blockIdx.z;
    const int blockM = blockIdx.y * 128, blockN = blockIdx.x * 128;

    float acc[2][8][4];
    #pragma unroll
    for (int i = 0; i < 2; ++i)
        #pragma unroll
        for (int j = 0; j < 8; ++j)
            #pragma unroll
            for (int c = 0; c < 4; ++c) acc[i][j][c] = 0.f;

    gemm_core(g_xt + (size_t)blockM * EE,
              g_wt + (size_t)z * WN + (size_t)blockN * EE, acc, sm);

    float* dst = (z == 0) ? g_q : (z == 1) ? g_k : g_v;
    const float scl = (z == 0) ? 0.125f : 1.0f;
    const int wid = threadIdx.x >> 5, lane = threadIdx.x & 31;
    const int grp = lane >> 2, tig = lane & 3;
    const int warpM = (wid & 3) * 32, warpN = (wid >> 2) * 64;

    #pragma unroll
    for (int i = 0; i < 2; ++i) {
        #pragma unroll
        for (int j = 0; j < 8; ++j) {
            const int col = blockN + warpN + j*8 + tig*2;
            const int h = col >> 6, d = col & 63;
            #pragma unroll
            for (int rh = 0; rh < 2; ++rh) {
                const int row = blockM + warpM + i*16 + grp + rh*8;
                const int b = row >> 10, t = row & (TT-1);
                float2 v2 = make_float2(
                    __uint_as_float(f2tf32(acc[i][j][rh*2]   * scl)),
                    __uint_as_float(f2tf32(acc[i][j][rh*2+1] * scl)));
                *(float2*)&dst[((size_t)(b*HH + h)*TT + t)*HSZ + d] = v2;
            }
        }
    }
}

__global__ __launch_bounds__(256, 2) void proj_gemm_kernel(float* __restrict__ out)
{
    extern __shared__ __align__(16) float sm[];
    const int blockM = blockIdx.y * 128, blockN = blockIdx.x * 128;

    float acc[2][8][4];
    #pragma unroll
    for (int i = 0; i < 2; ++i)
        #pragma unroll
        for (int j = 0; j < 8; ++j)
            #pragma unroll
            for (int c = 0; c < 4; ++c) acc[i][j][c] = 0.f;

    gemm_core(g_att + (size_t)blockM * EE,
              g_wt + 3 * WN + (size_t)blockN * EE, acc, sm);

    const int wid = threadIdx.x >> 5, lane = threadIdx.x & 31;
    const int grp = lane >> 2, tig = lane & 3;
    const int warpM = (wid & 3) * 32, warpN = (wid >> 2) * 64;

    #pragma unroll
    for (int i = 0; i < 2; ++i) {
        #pragma unroll
        for (int j = 0; j < 8; ++j) {
            const int col = blockN + warpN + j*8 + tig*2;
            #pragma unroll
            for (int rh = 0; rh < 2; ++rh) {
                const int row = blockM + warpM + i*16 + grp + rh*8;
                float2 v2 = make_float2(acc[i][j][rh*2], acc[i][j][rh*2+1]);
                *(float2*)&out[(size_t)row*EE + col] = v2;
            }
        }
    }
}

// ---------------------------------------------------------------------------
// Causal flash attention, mma.sync tf32. Inputs pre-rounded (+Q pre-scaled):
// staging is pure cp.async. V kept [s][d] (VLDW=68, conflict-free scalar
// b-fragment loads) -> no transpose stores.
// ---------------------------------------------------------------------------
#define ALDW 72
#define VLDW 68
#define ASMEM ((128*ALDW + 64*ALDW + 64*VLDW + 128*ALDW) * 4)

__global__ __launch_bounds__(256, 2) void attn_mma_kernel()
{
    extern __shared__ __align__(16) float sm[];
    float* Qs = sm;                   // [128][ALDW]
    float* Ks = Qs + 128 * ALDW;      // [64][ALDW]
    float* Vs = Ks + 64 * ALDW;       // [64][VLDW]  V[s][d]
    float* Ps = Vs + 64 * VLDW;       // [128][ALDW]

    const int qb = blockIdx.x, h = blockIdx.y, b = blockIdx.z;
    const float* qp = g_q + ((size_t)(b * HH + h) * TT + qb * 128) * HSZ;
    const float* kp = g_k + ((size_t)(b * HH + h) * TT) * HSZ;
    const float* vp = g_v + ((size_t)(b * HH + h) * TT) * HSZ;

    const int tid  = threadIdx.x;
    const int wid  = tid >> 5;
    const int lane = tid & 31;
    const int grp  = lane >> 2;
    const int tig  = lane & 3;
    const int wm   = wid * 16;
    const uint32_t sb = s2u(sm);
    const uint32_t sbK = sb + 128 * ALDW * 4;
    const uint32_t sbV = sbK + 64 * ALDW * 4;

    // stage Q via cp.async (2048 chunks, 8/thread); committed with first KV
    #pragma unroll
    for (int u = 0; u < 8; ++u) {
        const int i = tid + u * 256;
        const int row = i >> 4, cq = (i & 15) * 4;
        cpa16(sb + (uint32_t)(row * ALDW + cq) * 4,
              qp + (size_t)row * HSZ + cq);
    }

    float m[2], l[2], o[8][4];
    m[0] = m[1] = -1e30f; l[0] = l[1] = 0.f;
    #pragma unroll
    for (int j = 0; j < 8; ++j)
        #pragma unroll
        for (int c = 0; c < 4; ++c) o[j][c] = 0.f;

    const int ntiles = 2 * qb + 2;

    for (int kt = 0; kt < ntiles; ++kt) {
        // stage K [s][ALDW] and V [s][VLDW] via cp.async (4+4 chunks/thread)
        #pragma unroll
        for (int u = 0; u < 4; ++u) {
            const int i = tid + u * 256;
            const int s = i >> 4, cq = (i & 15) * 4;
            const size_t go = (size_t)(kt * 64 + s) * HSZ + cq;
            cpa16(sbK + (uint32_t)(s * ALDW + cq) * 4, kp + go);
            cpa16(sbV + (uint32_t)(s * VLDW + cq) * 4, vp + go);
        }
        CP_COMMIT();
        CP_WAIT0();
        __syncthreads();

        // S = Q K^T
        float sacc[8][4];
        #pragma unroll
        for (int j = 0; j < 8; ++j)
            #pragma unroll
            for (int c = 0; c < 4; ++c) sacc[j][c] = 0.f;

        #pragma unroll
        for (int kc = 0; kc < 8; ++kc) {
            const int koff = kc * 8 + 2 * tig;
            float2 a02 = *(const float2*)&Qs[(wm + grp    ) * ALDW + koff];
            float2 a13 = *(const float2*)&Qs[(wm + grp + 8) * ALDW + koff];
            #pragma unroll
            for (int j = 0; j < 8; ++j) {
                float2 b01 = *(const float2*)&Ks[(j * 8 + grp) * ALDW + koff];
                mma_tf32(sacc[j],
                    __float_as_uint(a02.x), __float_as_uint(a13.x),
                    __float_as_uint(a02.y), __float_as_uint(a13.y),
                    __float_as_uint(b01.x), __float_as_uint(b01.y));
            }
        }

        if (kt >= 2 * qb) {   // diagonal-straddling: causal mask
            #pragma unroll
            for (int j = 0; j < 8; ++j)
                #pragma unroll
                for (int c = 0; c < 4; ++c) {
                    const int row = qb * 128 + wm + grp + (c >> 1) * 8;
                    const int col = kt * 64 + j * 8 + 2 * tig + (c & 1);
                    if (col > row) sacc[j][c] = -1e30f;
                }
        }

        // online softmax
        float alpha[2];
        #pragma unroll
        for (int rh = 0; rh < 2; ++rh) {
            float rm = -1e30f;
            #pragma unroll
            for (int j = 0; j < 8; ++j)
                rm = fmaxf(rm, fmaxf(sacc[j][rh*2], sacc[j][rh*2+1]));
            rm = fmaxf(rm, __shfl_xor_sync(0xffffffffu, rm, 1));
            rm = fmaxf(rm, __shfl_xor_sync(0xffffffffu, rm, 2));
            const float mn = fmaxf(m[rh], rm);
            alpha[rh] = __expf(m[rh] - mn);
            m[rh] = mn;
            float rs = 0.f;
            #pragma unroll
            for (int j = 0; j < 8; ++j) {
                float p0 = __expf(sacc[j][rh*2  ] - mn);
                float p1 = __expf(sacc[j][rh*2+1] - mn);
                sacc[j][rh*2] = p0; sacc[j][rh*2+1] = p1;
                rs += p0 + p1;
            }
            rs += __shfl_xor_sync(0xffffffffu, rs, 1);
            rs += __shfl_xor_sync(0xffffffffu, rs, 2);
            l[rh] = l[rh] * alpha[rh] + rs;
            #pragma unroll
            for (int j = 0; j < 8; ++j) {
                o[j][rh*2]   *= alpha[rh];
                o[j][rh*2+1] *= alpha[rh];
            }
        }

        __syncthreads();
        // P -> smem (STS.64)
        #pragma unroll
        for (int j = 0; j < 8; ++j) {
            #pragma unroll
            for (int rh = 0; rh < 2; ++rh) {
                const int row = wm + grp + rh * 8;
                float2 p2 = make_float2(
                    __uint_as_float(f2tf32(sacc[j][rh*2])),
                    __uint_as_float(f2tf32(sacc[j][rh*2+1])));
                *(float2*)&Ps[row * ALDW + j * 8 + 2 * tig] = p2;
            }
        }
        __syncthreads();

        // O += P V ; b-fragment from V[s][d]: two scalar loads, stride VLDW
        #pragma unroll
        for (int ss = 0; ss < 8; ++ss) {
            const int koff = ss * 8 + 2 * tig;
            float2 a02 = *(const float2*)&Ps[(wm + grp    ) * ALDW + koff];
            float2 a13 = *(const float2*)&Ps[(wm + grp + 8) * ALDW + koff];
            #pragma unroll
            for (int j = 0; j < 8; ++j) {
                const int col = j * 8 + grp;
                const float b0 = Vs[koff * VLDW + col];
                const float b1 = Vs[(koff + 1) * VLDW + col];
                mma_tf32(o[j],
                    __float_as_uint(a02.x), __float_as_uint(a13.x),
                    __float_as_uint(a02.y), __float_as_uint(a13.y),
                    __float_as_uint(b0),    __float_as_uint(b1));
            }
        }
        __syncthreads();
    }

    // normalize + store tf32-rounded for proj GEMM
    const float inv0 = 1.0f / l[0];
    const float inv1 = 1.0f / l[1];
    #pragma unroll
    for (int j = 0; j < 8; ++j) {
        const int col = h * HSZ + j * 8 + 2 * tig;
        #pragma unroll
        for (int rh = 0; rh < 2; ++rh) {
            const float inv = rh ? inv1 : inv0;
            const int row = qb * 128 + wm + grp + rh * 8;
            float2 v2 = make_float2(
                __uint_as_float(f2tf32(o[j][rh*2]   * inv)),
                __uint_as_float(f2tf32(o[j][rh*2+1] * inv)));
            *(float2*)&g_att[((size_t)b * TT + row) * EE + col] = v2;
        }
    }
}

// ---------------------------------------------------------------------------
extern "C" void kernel_launch(void* const* d_in, const int* in_sizes, int n_in,
                              void* d_out, int out_size)
{
    const float* x  = (const float*)d_in[0];
    const float* Wk = (const float*)d_in[1];
    const float* Wq = (const float*)d_in[2];
    const float* Wv = (const float*)d_in[3];
    const float* Wp = (const float*)d_in[4];
    float* out = (float*)d_out;

    cudaFuncSetAttribute(qkv_gemm_kernel,
                         cudaFuncAttributeMaxDynamicSharedMemorySize, GSMEM);
    cudaFuncSetAttribute(proj_gemm_kernel,
                         cudaFuncAttributeMaxDynamicSharedMemorySize, GSMEM);
    cudaFuncSetAttribute(attn_mma_kernel,
                         cudaFuncAttributeMaxDynamicSharedMemorySize, ASMEM);

    const size_t total4 = (XN + 4 * WN) / 4;
    round_tf32_kernel<<<(unsigned)((total4 + 255) / 256), 256>>>(x, Wq, Wk, Wv, Wp);

    qkv_gemm_kernel<<<dim3(EE / 128, MTOT / 128, 3), 256, GSMEM>>>();

    attn_mma_kernel<<<dim3(TT / 128, HH, BB), 256, ASMEM>>>();

    proj_gemm_kernel<<<dim3(EE / 128, MTOT / 128), 256, GSMEM>>>(out);
}